// round 3
// baseline (speedup 1.0000x reference)
#include <cuda_runtime.h>
#include <cstdint>

// Problem constants (B=2, S=2048, H=1024, I=2048, E=8, K=2)
#define TOKENS 4096
#define HDIM   1024
#define IDIM   2048
#define NEXP   8

// ---------------- device scratch (static globals; no runtime allocation) ----
__device__ int   g_cnt[NEXP];
__device__ int   g_off[NEXP];
__device__ int   g_tok[NEXP * TOKENS];
__device__ float g_cw [NEXP * TOKENS];
__device__ float g_probs[TOKENS * NEXP];
// hidden activations after SwiGLU: 8192 rows x 2048 cols fp32 = 64 MB
__device__ float g_hbuf[(size_t)(2 * TOKENS) * IDIM];

// ---------------- packed f32x2 FMA (Blackwell full-rate FP32 path) ----------
__device__ __forceinline__ unsigned long long ffma2(unsigned long long a,
                                                    unsigned long long b,
                                                    unsigned long long c) {
    unsigned long long d;
    asm("fma.rn.f32x2 %0, %1, %2, %3;" : "=l"(d) : "l"(a), "l"(b), "l"(c));
    return d;
}

__device__ __forceinline__ float2 u2f(unsigned long long v) {
    float2 f;
    f.x = __uint_as_float((unsigned)(v & 0xffffffffull));
    f.y = __uint_as_float((unsigned)(v >> 32));
    return f;
}

// ---------------- tiny kernels ----------------------------------------------
__global__ void init_kernel() {
    int i = threadIdx.x;
    if (i < NEXP) g_cnt[i] = 0;
}

__global__ void offsets_kernel() {
    int s = 0;
    for (int e = 0; e < NEXP; e++) { g_off[e] = s; s += g_cnt[e]; }
}

// ---------------- router: logits -> softmax -> top2 -> assignment -----------
// one warp per token; grid = TOKENS/4 blocks of 128 threads
__global__ void router_kernel(const float* __restrict__ x,
                              const float* __restrict__ Wr) {
    int t    = blockIdx.x * 4 + (threadIdx.x >> 5);
    int lane = threadIdx.x & 31;
    const float* xr = x + (size_t)t * HDIM;

    float acc[NEXP];
#pragma unroll
    for (int e = 0; e < NEXP; e++) acc[e] = 0.f;

    for (int h = lane; h < HDIM; h += 32) {
        float xv = xr[h];
        const float* w = Wr + h * NEXP;
#pragma unroll
        for (int e = 0; e < NEXP; e++) acc[e] += xv * w[e];
    }
#pragma unroll
    for (int e = 0; e < NEXP; e++) {
#pragma unroll
        for (int o = 16; o; o >>= 1)
            acc[e] += __shfl_xor_sync(0xffffffffu, acc[e], o);
    }

    if (lane == 0) {
        float mx = acc[0];
#pragma unroll
        for (int e = 1; e < NEXP; e++) mx = fmaxf(mx, acc[e]);
        float p[NEXP];
        float s = 0.f;
#pragma unroll
        for (int e = 0; e < NEXP; e++) { p[e] = expf(acc[e] - mx); s += p[e]; }
        float inv = 1.f / s;
#pragma unroll
        for (int e = 0; e < NEXP; e++) {
            p[e] *= inv;
            g_probs[t * NEXP + e] = p[e];
        }
        // top-2 (ties -> lowest index first, matching lax.top_k)
        int i1 = 0; float p1 = p[0];
#pragma unroll
        for (int e = 1; e < NEXP; e++) if (p[e] > p1) { p1 = p[e]; i1 = e; }
        int i2 = -1; float p2 = -1.f;
#pragma unroll
        for (int e = 0; e < NEXP; e++)
            if (e != i1 && p[e] > p2) { p2 = p[e]; i2 = e; }
        float winv = 1.f / (p1 + p2);
        float w1v = p1 * winv, w2v = p2 * winv;

        int pos1 = atomicAdd(&g_cnt[i1], 1);
        g_tok[i1 * TOKENS + pos1] = t;
        g_cw [i1 * TOKENS + pos1] = w1v;
        int pos2 = atomicAdd(&g_cnt[i2], 1);
        g_tok[i2 * TOKENS + pos2] = t;
        g_cw [i2 * TOKENS + pos2] = w2v;
    }
}

// ---------------- aux loss (deterministic reduction) -------------------------
__global__ void aux_kernel(float* __restrict__ out, int aux_idx) {
    __shared__ float sh[256];
    int tid = threadIdx.x;
    float a[NEXP];
#pragma unroll
    for (int e = 0; e < NEXP; e++) a[e] = 0.f;
    for (int t = tid; t < TOKENS; t += 256) {
#pragma unroll
        for (int e = 0; e < NEXP; e++) a[e] += g_probs[t * NEXP + e];
    }
    float loss = 0.f;
    for (int e = 0; e < NEXP; e++) {
        sh[tid] = a[e];
        __syncthreads();
        for (int s = 128; s; s >>= 1) {
            if (tid < s) sh[tid] += sh[tid + s];
            __syncthreads();
        }
        if (tid == 0) {
            float u = sh[0] * (1.f / TOKENS) - (1.f / NEXP);
            loss += u * u;
        }
        __syncthreads();
    }
    if (tid == 0) out[aux_idx] = loss * 0.01f;
}

// ---------------- GEMM 1: h = silu(X_e @ w1[e]) * (X_e @ w2[e]) --------------
// Tile 128(M) x 64(N) x 16(K), 256 threads, 8x4 per thread (as f32x2 pairs),
// A rows gathered via g_tok, both B matrices share the A tile.
__global__ __launch_bounds__(256, 2)
void gemm1_kernel(const float* __restrict__ x,
                  const float* __restrict__ w1,
                  const float* __restrict__ w2) {
    const int e   = blockIdx.z;
    const int cnt = g_cnt[e];
    const int m0  = blockIdx.x * 128;
    if (m0 >= cnt) return;
    const int n0  = blockIdx.y * 64;
    const int off = g_off[e];

    __shared__ float2 As[16][128];   // A duplicated: (v,v) pairs
    __shared__ float  Bs1[16][64];
    __shared__ float  Bs2[16][64];

    const int tid = threadIdx.x;
    const int tx = tid & 15, ty = tid >> 4;

    // A loader: each thread loads two float4s (rows 0-63 and 64-127)
    const int arow0 = tid >> 2, ac0 = (tid & 3) * 4;
    const int arow1 = arow0 + 64;
    const int r0 = m0 + arow0, r1 = m0 + arow1;
    const float* ap0 = (r0 < cnt) ? x + (size_t)g_tok[e * TOKENS + r0] * HDIM : nullptr;
    const float* ap1 = (r1 < cnt) ? x + (size_t)g_tok[e * TOKENS + r1] * HDIM : nullptr;

    // B loader: one float4 per thread per matrix
    const int kr = tid >> 4, c4 = (tid & 15) * 4;
    const float* b1p = w1 + (size_t)e * HDIM * IDIM + (size_t)kr * IDIM + n0 + c4;
    const float* b2p = w2 + (size_t)e * HDIM * IDIM + (size_t)kr * IDIM + n0 + c4;

    unsigned long long accG[8][2], accU[8][2];
#pragma unroll
    for (int i = 0; i < 8; i++)
#pragma unroll
        for (int j = 0; j < 2; j++) { accG[i][j] = 0ull; accU[i][j] = 0ull; }

    const float4 z4 = make_float4(0.f, 0.f, 0.f, 0.f);

    for (int kb = 0; kb < HDIM; kb += 16) {
        float4 av0 = ap0 ? *(const float4*)(ap0 + kb + ac0) : z4;
        float4 av1 = ap1 ? *(const float4*)(ap1 + kb + ac0) : z4;
        float4 bv1 = *(const float4*)(b1p + (size_t)kb * IDIM);
        float4 bv2 = *(const float4*)(b2p + (size_t)kb * IDIM);
        __syncthreads();
        As[ac0 + 0][arow0] = make_float2(av0.x, av0.x);
        As[ac0 + 1][arow0] = make_float2(av0.y, av0.y);
        As[ac0 + 2][arow0] = make_float2(av0.z, av0.z);
        As[ac0 + 3][arow0] = make_float2(av0.w, av0.w);
        As[ac0 + 0][arow1] = make_float2(av1.x, av1.x);
        As[ac0 + 1][arow1] = make_float2(av1.y, av1.y);
        As[ac0 + 2][arow1] = make_float2(av1.z, av1.z);
        As[ac0 + 3][arow1] = make_float2(av1.w, av1.w);
        *(float4*)&Bs1[kr][c4] = bv1;
        *(float4*)&Bs2[kr][c4] = bv2;
        __syncthreads();

#pragma unroll
        for (int k = 0; k < 16; k++) {
            unsigned long long a[8];
            const unsigned long long* ap = (const unsigned long long*)&As[k][ty * 8];
#pragma unroll
            for (int i = 0; i < 8; i++) a[i] = ap[i];
            unsigned long long b1a = *(const unsigned long long*)&Bs1[k][tx * 4];
            unsigned long long b1b = *(const unsigned long long*)&Bs1[k][tx * 4 + 2];
            unsigned long long b2a = *(const unsigned long long*)&Bs2[k][tx * 4];
            unsigned long long b2b = *(const unsigned long long*)&Bs2[k][tx * 4 + 2];
#pragma unroll
            for (int i = 0; i < 8; i++) {
                accG[i][0] = ffma2(a[i], b1a, accG[i][0]);
                accG[i][1] = ffma2(a[i], b1b, accG[i][1]);
                accU[i][0] = ffma2(a[i], b2a, accU[i][0]);
                accU[i][1] = ffma2(a[i], b2b, accU[i][1]);
            }
        }
    }

    // epilogue: h = silu(g) * u
#pragma unroll
    for (int i = 0; i < 8; i++) {
        int m = m0 + ty * 8 + i;
        if (m >= cnt) continue;
        float* hp = g_hbuf + (size_t)(off + m) * IDIM + n0 + tx * 4;
#pragma unroll
        for (int j = 0; j < 2; j++) {
            float2 g = u2f(accG[i][j]);
            float2 u = u2f(accU[i][j]);
            float h0 = (g.x / (1.f + expf(-g.x))) * u.x;
            float h1 = (g.y / (1.f + expf(-g.y))) * u.y;
            *(float2*)(hp + 2 * j) = make_float2(h0, h1);
        }
    }
}

// ---------------- GEMM 2: out[tok] += cw * (h_e @ w3[e]) ---------------------
__global__ __launch_bounds__(256, 2)
void gemm2_kernel(const float* __restrict__ w3, float* __restrict__ out) {
    const int e   = blockIdx.z;
    const int cnt = g_cnt[e];
    const int m0  = blockIdx.x * 128;
    if (m0 >= cnt) return;
    const int n0  = blockIdx.y * 64;
    const int off = g_off[e];

    __shared__ float2 As[16][128];
    __shared__ float  Bs[16][64];

    const int tid = threadIdx.x;
    const int tx = tid & 15, ty = tid >> 4;

    const int arow0 = tid >> 2, ac0 = (tid & 3) * 4;
    const int arow1 = arow0 + 64;
    const float* ap0 = (m0 + arow0 < cnt)
        ? g_hbuf + (size_t)(off + m0 + arow0) * IDIM : nullptr;
    const float* ap1 = (m0 + arow1 < cnt)
        ? g_hbuf + (size_t)(off + m0 + arow1) * IDIM : nullptr;

    const int kr = tid >> 4, c4 = (tid & 15) * 4;
    const float* bp = w3 + (size_t)e * IDIM * HDIM + (size_t)kr * HDIM + n0 + c4;

    unsigned long long acc[8][2];
#pragma unroll
    for (int i = 0; i < 8; i++) { acc[i][0] = 0ull; acc[i][1] = 0ull; }

    const float4 z4 = make_float4(0.f, 0.f, 0.f, 0.f);

    for (int kb = 0; kb < IDIM; kb += 16) {
        float4 av0 = ap0 ? *(const float4*)(ap0 + kb + ac0) : z4;
        float4 av1 = ap1 ? *(const float4*)(ap1 + kb + ac0) : z4;
        float4 bv  = *(const float4*)(bp + (size_t)kb * HDIM);
        __syncthreads();
        As[ac0 + 0][arow0] = make_float2(av0.x, av0.x);
        As[ac0 + 1][arow0] = make_float2(av0.y, av0.y);
        As[ac0 + 2][arow0] = make_float2(av0.z, av0.z);
        As[ac0 + 3][arow0] = make_float2(av0.w, av0.w);
        As[ac0 + 0][arow1] = make_float2(av1.x, av1.x);
        As[ac0 + 1][arow1] = make_float2(av1.y, av1.y);
        As[ac0 + 2][arow1] = make_float2(av1.z, av1.z);
        As[ac0 + 3][arow1] = make_float2(av1.w, av1.w);
        *(float4*)&Bs[kr][c4] = bv;
        __syncthreads();

#pragma unroll
        for (int k = 0; k < 16; k++) {
            unsigned long long a[8];
            const unsigned long long* ap = (const unsigned long long*)&As[k][ty * 8];
#pragma unroll
            for (int i = 0; i < 8; i++) a[i] = ap[i];
            unsigned long long ba = *(const unsigned long long*)&Bs[k][tx * 4];
            unsigned long long bb = *(const unsigned long long*)&Bs[k][tx * 4 + 2];
#pragma unroll
            for (int i = 0; i < 8; i++) {
                acc[i][0] = ffma2(a[i], ba, acc[i][0]);
                acc[i][1] = ffma2(a[i], bb, acc[i][1]);
            }
        }
    }

    // epilogue: weighted scatter-add (exactly 2 commutative adds per element)
#pragma unroll
    for (int i = 0; i < 8; i++) {
        int m = m0 + ty * 8 + i;
        if (m >= cnt) continue;
        int   tok = g_tok[e * TOKENS + m];
        float cw  = g_cw [e * TOKENS + m];
        float* op = out + (size_t)tok * HDIM + n0 + tx * 4;
#pragma unroll
        for (int j = 0; j < 2; j++) {
            float2 v = u2f(acc[i][j]);
            atomicAdd(op + 2 * j + 0, cw * v.x);
            atomicAdd(op + 2 * j + 1, cw * v.y);
        }
    }
}

// ---------------- launch -----------------------------------------------------
extern "C" void kernel_launch(void* const* d_in, const int* in_sizes, int n_in,
                              void* d_out, int out_size) {
    const float* x  = (const float*)d_in[0];
    const float* Wr = (const float*)d_in[1];
    const float* w1 = (const float*)d_in[2];
    const float* w2 = (const float*)d_in[3];
    const float* w3 = (const float*)d_in[4];
    float* out = (float*)d_out;

    cudaMemsetAsync(d_out, 0, (size_t)out_size * sizeof(float));
    init_kernel<<<1, 32>>>();
    router_kernel<<<TOKENS / 4, 128>>>(x, Wr);
    offsets_kernel<<<1, 1>>>();
    aux_kernel<<<1, 256>>>(out, out_size - 1);
    gemm1_kernel<<<dim3(TOKENS / 128, IDIM / 64, NEXP), 256>>>(x, w1, w2);
    gemm2_kernel<<<dim3(TOKENS / 128, HDIM / 64, NEXP), 256>>>(w3, out);
}